// round 3
// baseline (speedup 1.0000x reference)
#include <cuda_runtime.h>
#include <cuda_bf16.h>
#include <cstdint>

#define N_NODES 100000
#define N_EDGES 1000000
#define IN_CH   128
#define OUT_CH  128
#define T_DIM   64
#define AGG_W   192   // 128 (x-sum) + 64 (tf-sum)

// ---------------- device scratch (no allocation allowed) ----------------
__device__ __align__(16) float g_agg[(size_t)N_NODES * AGG_W];
__device__ __align__(16) float g_deg[N_NODES];
__device__ __align__(16) float g_Wt[320 * 128];   // combined transposed weight [k][o]
__device__ __align__(16) float g_cb[128];         // W_T_b + T_b
__device__ int g_idx_is64;                        // 1 if edge_index is int64 layout

// ---------------- helpers ----------------
__device__ __forceinline__ void red_add_v4(float* p, float4 v) {
    unsigned long long gp = __cvta_generic_to_global((void*)p);
    asm volatile("red.global.add.v4.f32 [%0], {%1,%2,%3,%4};"
                 :: "l"(gp), "f"(v.x), "f"(v.y), "f"(v.z), "f"(v.w)
                 : "memory");
}

// ---------------- kernel 0: detect edge_index dtype ----------------
// If data is int64 (values < 2^31, nonnegative), every odd 32-bit word is 0.
// If data is int32, odd words are real indices: P(4096 all zero) ~ 0.
__global__ void detect_kernel(const int* __restrict__ ei_raw) {
    __shared__ int any_nonzero;
    if (threadIdx.x == 0) any_nonzero = 0;
    __syncthreads();
    for (int i = threadIdx.x; i < 4096; i += blockDim.x)
        if (ei_raw[2 * i + 1] != 0) any_nonzero = 1;
    __syncthreads();
    if (threadIdx.x == 0) g_idx_is64 = (any_nonzero == 0);
}

// ---------------- kernel 1: build combined transposed weights ----------------
__global__ void prep_kernel(const float* __restrict__ Wsw,
                            const float* __restrict__ Wtw,
                            const float* __restrict__ Tw,
                            const float* __restrict__ Wtb,
                            const float* __restrict__ Tb) {
    int tid = blockIdx.x * blockDim.x + threadIdx.x;
    if (tid < 320 * 128) {
        int k = tid >> 7;       // /128
        int o = tid & 127;
        float v;
        if (k < 128)       v = Wsw[o * 128 + k];
        else if (k < 256)  v = Wtw[o * 128 + (k - 128)];
        else               v = Tw[o * 64 + (k - 256)];
        g_Wt[k * 128 + o] = v;
    }
    if (tid < 128) g_cb[tid] = Wtb[tid] + Tb[tid];
}

// ---------------- kernel 2: zero accumulators ----------------
__global__ void zero_kernel() {
    const size_t n4_agg = (size_t)N_NODES * AGG_W / 4;
    const size_t n4_deg = N_NODES / 4;
    float4 z = make_float4(0.f, 0.f, 0.f, 0.f);
    size_t stride = (size_t)gridDim.x * blockDim.x;
    for (size_t i = blockIdx.x * (size_t)blockDim.x + threadIdx.x; i < n4_agg; i += stride)
        ((float4*)g_agg)[i] = z;
    for (size_t i = blockIdx.x * (size_t)blockDim.x + threadIdx.x; i < n4_deg; i += stride)
        ((float4*)g_deg)[i] = z;
}

// ---------------- kernel 3: edge scatter-add (one warp per edge) ----------------
__global__ void edge_kernel(const void* __restrict__ ei_raw,
                            const float* __restrict__ x,
                            const float* __restrict__ tf) {
    int warp = (blockIdx.x * blockDim.x + threadIdx.x) >> 5;
    int lane = threadIdx.x & 31;
    if (warp >= N_EDGES) return;

    int row, col;
    if (g_idx_is64) {
        const long long* ei = (const long long*)ei_raw;
        row = (int)__ldg(&ei[warp]);              // same addr across warp: broadcast
        col = (int)__ldg(&ei[N_EDGES + warp]);
    } else {
        const int* ei = (const int*)ei_raw;
        row = __ldg(&ei[warp]);
        col = __ldg(&ei[N_EDGES + warp]);
    }
    if ((unsigned)row >= N_NODES || (unsigned)col >= N_NODES) return; // defensive

    // gather x[col] (128 floats = 32 x float4, one per lane) and scatter-add
    const float4* xs = (const float4*)(x + (size_t)col * IN_CH);
    float4 vx = xs[lane];
    float* aggrow = g_agg + (size_t)row * AGG_W;
    red_add_v4(aggrow + lane * 4, vx);

    // temporal features: 64 floats = 16 x float4 (lanes 0..15)
    if (lane < 16) {
        const float4* ts = (const float4*)(tf + (size_t)warp * T_DIM);
        red_add_v4(aggrow + IN_CH + lane * 4, ts[lane]);
    }
    if (lane == 0) atomicAdd(&g_deg[row], 1.0f);
}

// ---------------- kernel 4: node GEMM + bias + relu ----------------
// C[100000][128] = relu( A[100000][320] @ g_Wt[320][128] + W_S_b + deg * g_cb )
// A row = concat(x[node][0:128], g_agg[node][0:192])
#define BM 64
#define BN 128
#define BK 32

__global__ __launch_bounds__(256) void gemm_kernel(const float* __restrict__ x,
                                                   const float* __restrict__ Wsb,
                                                   float* __restrict__ out) {
    __shared__ float As[BK][BM + 1];
    __shared__ float Bs[BK][BN];

    int m0 = blockIdx.x * BM;
    int tid = threadIdx.x;
    int tn = (tid & 31) * 4;    // n offset: 0..124
    int tm = (tid >> 5) * 8;    // m offset: 0..56 (warp-uniform -> LDS broadcast)

    float acc[8][4];
#pragma unroll
    for (int i = 0; i < 8; i++)
#pragma unroll
        for (int j = 0; j < 4; j++) acc[i][j] = 0.f;

    for (int k0 = 0; k0 < 320; k0 += BK) {
        // ---- load A tile: [64 m][32 k], coalesced on k ----
#pragma unroll
        for (int i = 0; i < 8; i++) {
            int e = tid + i * 256;
            int m = e >> 5, k = e & 31;
            int node = m0 + m;
            float v = 0.f;
            int gk = k0 + k;
            if (node < N_NODES) {
                v = (gk < 128) ? x[(size_t)node * IN_CH + gk]
                               : g_agg[(size_t)node * AGG_W + (gk - 128)];
            }
            As[k][m] = v;
        }
        // ---- load B tile: [32 k][128 n] via float4 ----
#pragma unroll
        for (int i = 0; i < 4; i++) {
            int f = tid + i * 256;
            int k = f >> 5, n4 = f & 31;
            float4 w = ((const float4*)(g_Wt + (size_t)(k0 + k) * 128))[n4];
            *((float4*)&Bs[k][n4 * 4]) = w;
        }
        __syncthreads();

#pragma unroll
        for (int kk = 0; kk < BK; kk++) {
            float4 bb = *((const float4*)&Bs[kk][tn]);
#pragma unroll
            for (int i = 0; i < 8; i++) {
                float a = As[kk][tm + i];
                acc[i][0] += a * bb.x;
                acc[i][1] += a * bb.y;
                acc[i][2] += a * bb.z;
                acc[i][3] += a * bb.w;
            }
        }
        __syncthreads();
    }

    // ---- epilogue: + W_S_b + deg*(W_T_b+T_b), relu, store ----
    float4 bsb = ((const float4*)Wsb)[tn >> 2];
    float4 cb4 = ((const float4*)g_cb)[tn >> 2];
#pragma unroll
    for (int i = 0; i < 8; i++) {
        int node = m0 + tm + i;
        if (node < N_NODES) {
            float d = g_deg[node];
            float4 o;
            o.x = acc[i][0] + bsb.x + d * cb4.x;
            o.y = acc[i][1] + bsb.y + d * cb4.y;
            o.z = acc[i][2] + bsb.z + d * cb4.z;
            o.w = acc[i][3] + bsb.w + d * cb4.w;
            o.x = o.x > 0.f ? o.x : 0.f;
            o.y = o.y > 0.f ? o.y : 0.f;
            o.z = o.z > 0.f ? o.z : 0.f;
            o.w = o.w > 0.f ? o.w : 0.f;
            ((float4*)(out + (size_t)node * OUT_CH))[tn >> 2] = o;
        }
    }
}

// ---------------- launcher ----------------
extern "C" void kernel_launch(void* const* d_in, const int* in_sizes, int n_in,
                              void* d_out, int out_size) {
    // Identify inputs by element count (unique sizes except the two [128,128]
    // weights and the three [128] biases, which keep reference order).
    const float* x = nullptr; const void* ei = nullptr; const float* tf = nullptr;
    const float* Wsw = nullptr; const float* Wsb = nullptr;
    const float* Wtw = nullptr; const float* Wtb = nullptr;
    const float* Tw = nullptr;  const float* Tb = nullptr;
    int n16384 = 0, n128 = 0;
    for (int i = 0; i < n_in; i++) {
        long long s = in_sizes[i];
        void* p = d_in[i];
        if (s == (long long)N_NODES * IN_CH)      x  = (const float*)p;
        else if (s == 2LL * N_EDGES)              ei = (const void*)p;
        else if (s == (long long)N_EDGES * T_DIM) tf = (const float*)p;
        else if (s == OUT_CH * T_DIM)             Tw = (const float*)p;
        else if (s == OUT_CH * IN_CH) {
            if (n16384++ == 0) Wsw = (const float*)p; else Wtw = (const float*)p;
        } else if (s == OUT_CH) {
            if (n128 == 0) Wsb = (const float*)p;
            else if (n128 == 1) Wtb = (const float*)p;
            else Tb = (const float*)p;
            n128++;
        }
    }
    float* out = (float*)d_out;

    detect_kernel<<<1, 256>>>((const int*)ei);
    prep_kernel<<<(320 * 128 + 255) / 256, 256>>>(Wsw, Wtw, Tw, Wtb, Tb);
    zero_kernel<<<2048, 256>>>();
    edge_kernel<<<N_EDGES / 8, 256>>>(ei, x, tf);
    gemm_kernel<<<(N_NODES + BM - 1) / BM, 256>>>(x, Wsb, out);
}